// round 15
// baseline (speedup 1.0000x reference)
#include <cuda_runtime.h>
#include <math.h>
#include <stdint.h>

#define SB   512
#define HH   320
#define GG   1280
#define TT   64
#define DIN1 48
#define DIN2 640

// ---------------- device scratch ----------------
__device__ float g_vfw[TT * SB * DIN1];
__device__ float g_XGA[TT * SB * GG];       // stage-1 xg (fwd)
__device__ float g_XGB[TT * SB * GG];       // stage-1 xg (rev)
__device__ float g_XGA2[TT * SB * GG];      // stage-2 xg (fwd)
__device__ float g_XGB2[TT * SB * GG];      // stage-2 xg (rev)
__device__ float g_vfm[TT * SB * 2 * HH];
__device__ float g_hfm[SB * TT * 2 * HH];
__device__ float g_state[4 * SB * HH];
__device__ float g_gates[4 * SB * GG];      // recurrent split-K partials
__device__ float g_pool[SB * 128 * 15 * 15];
__device__ float g_c2[SB * 48 * 12 * 12];
__device__ float g_d1[SB * 2048];
__device__ float g_d2[SB * 2048];
__device__ float g_part[8 * SB * 2048];     // dense1 split-K partials
__device__ float g_part2[4 * SB * 2048];    // dense2 split-K partials
__device__ float g_mean[128];
__device__ float g_istd[128];
__device__ float g_im2col[73728 * 2048];
__device__ float g_cc[73728 * 128];
__device__ float g_w2pad[128 * 2048];
__device__ float g_b2pad[128];

// ---------------- mma helpers ----------------
__device__ __forceinline__ uint32_t pack_bf16(float lo, float hi) {
    uint32_t r;
    asm("cvt.rn.bf16x2.f32 %0, %1, %2;" : "=r"(r) : "f"(hi), "f"(lo));
    return r;
}
__device__ __forceinline__ void mma_bf16(float* c, const uint32_t* a, const uint32_t* b) {
    asm volatile(
        "mma.sync.aligned.m16n8k16.row.col.f32.bf16.bf16.f32 "
        "{%0,%1,%2,%3}, {%4,%5,%6,%7}, {%8,%9}, {%0,%1,%2,%3};"
        : "+f"(c[0]), "+f"(c[1]), "+f"(c[2]), "+f"(c[3])
        : "r"(a[0]), "r"(a[1]), "r"(a[2]), "r"(a[3]), "r"(b[0]), "r"(b[1]));
}

#define BKC 32

// ---------------- bf16 GEMM: C[M,N] = A[M,K] @ B[N,K]^T ----------------
// recDual=1: blockIdx.z = (ks<<1)|lstm; K halves -> partial buffers.
// splitK>1 && kIdx>=0: single K-chunk kIdx, grid.z=1, C -> C0 + kIdx*M*N.
struct MArgs {
    const float *A0, *B0; float* C0;
    const float *A1, *B1; float* C1;
    int M, N, K;
    const float* bias; int relu;
    int splitK;
    int recDual;
    int kIdx;
};

__global__ __launch_bounds__(256) void bf16_gemm(MArgs p)
{
    __shared__ uint32_t As[2][2048];
    __shared__ uint32_t Bs[2][2048];

    const float *A, *B; float* C;
    int kOff = 0, kLen = p.K;
    if (p.recDual) {
        int lstm = blockIdx.z & 1, ks = blockIdx.z >> 1;
        A = lstm ? p.A1 : p.A0;
        B = lstm ? p.B1 : p.B0;
        kLen = p.K >> 1;
        kOff = ks * kLen;
        C = p.C0 + (size_t)(lstm + 2 * ks) * p.M * p.N;
    } else if (p.splitK > 1) {
        A = p.A0; B = p.B0;
        kLen = p.K / p.splitK;
        int z = (p.kIdx >= 0) ? p.kIdx : (int)blockIdx.z;
        kOff = z * kLen;
        C = p.C0 + (size_t)z * p.M * p.N;
    } else {
        A = blockIdx.z ? p.A1 : p.A0;
        B = blockIdx.z ? p.B1 : p.B0;
        C = blockIdx.z ? p.C1 : p.C0;
    }
    const int N = p.N, K = p.K;
    const int m0 = blockIdx.y * 128, n0 = blockIdx.x * 128;
    const int tid = threadIdx.x, lane = tid & 31, wid = tid >> 5;
    const int wr = wid & 3, wc = wid >> 2;
    const int kEnd = kOff + kLen;
    const int NC = (kLen + BKC - 1) / BKC;

    uint32_t aAd[4], bAd[4];
    int fr[4], fq[4];
#pragma unroll
    for (int i = 0; i < 4; i++) {
        int f = tid + i * 256;
        int r = f >> 3, q = f & 7;
        fr[i] = r; fq[i] = q;
        int kt = q >> 2;
        int ps = (2 * q) & 7;
        { int mt = r >> 4, r16 = r & 15;
          int laneA = (r16 & 7) * 4 + (ps & 3);
          int regA = (ps >> 2) * 2 + (r16 >> 3);
          aAd[i] = (uint32_t)(((kt * 8 + mt) * 32 + laneA) * 4 + regA); }
        { int nt = r >> 3, n8 = r & 7;
          int laneB = n8 * 4 + (ps & 3);
          int regB = ps >> 2;
          bAd[i] = (uint32_t)(((kt * 16 + nt) * 32 + laneB) * 2 + regB); }
    }

    float cacc[2][8][4];
#pragma unroll
    for (int i = 0; i < 2; i++)
#pragma unroll
        for (int j = 0; j < 8; j++)
#pragma unroll
            for (int v = 0; v < 4; v++) cacc[i][j][v] = 0.f;

    float4 pa[4], pb[4];
#pragma unroll
    for (int i = 0; i < 4; i++) {
        int gk = kOff + fq[i] * 4;
        pa[i] = make_float4(0.f, 0.f, 0.f, 0.f);
        pb[i] = pa[i];
        if (gk < kEnd) {
            pa[i] = *(const float4*)(A + (size_t)(m0 + fr[i]) * K + gk);
            pb[i] = *(const float4*)(B + (size_t)(n0 + fr[i]) * K + gk);
        }
    }
#pragma unroll
    for (int i = 0; i < 4; i++) {
        As[0][aAd[i]] = pack_bf16(pa[i].x, pa[i].y);
        As[0][aAd[i] + 4] = pack_bf16(pa[i].z, pa[i].w);
        Bs[0][bAd[i]] = pack_bf16(pb[i].x, pb[i].y);
        Bs[0][bAd[i] + 2] = pack_bf16(pb[i].z, pb[i].w);
    }
    __syncthreads();

    for (int ch = 0; ch < NC; ch++) {
        int pbuf = ch & 1;
        if (ch + 1 < NC) {
#pragma unroll
            for (int i = 0; i < 4; i++) {
                int gk = kOff + (ch + 1) * BKC + fq[i] * 4;
                pa[i] = make_float4(0.f, 0.f, 0.f, 0.f);
                pb[i] = pa[i];
                if (gk < kEnd) {
                    pa[i] = *(const float4*)(A + (size_t)(m0 + fr[i]) * K + gk);
                    pb[i] = *(const float4*)(B + (size_t)(n0 + fr[i]) * K + gk);
                }
            }
        }
        const uint32_t* Ab = As[pbuf];
        const uint32_t* Bb = Bs[pbuf];
#pragma unroll
        for (int kt = 0; kt < 2; kt++) {
            uint32_t af[2][4], bf[8][2];
#pragma unroll
            for (int i = 0; i < 2; i++) {
                int mt = wr * 2 + i;
                uint4 v = *(const uint4*)&Ab[((kt * 8 + mt) * 32 + lane) * 4];
                af[i][0] = v.x; af[i][1] = v.y; af[i][2] = v.z; af[i][3] = v.w;
            }
#pragma unroll
            for (int j = 0; j < 8; j++) {
                int nt = wc * 8 + j;
                uint2 v = *(const uint2*)&Bb[((kt * 16 + nt) * 32 + lane) * 2];
                bf[j][0] = v.x; bf[j][1] = v.y;
            }
#pragma unroll
            for (int i = 0; i < 2; i++)
#pragma unroll
                for (int j = 0; j < 8; j++)
                    mma_bf16(cacc[i][j], af[i], bf[j]);
        }
        if (ch + 1 < NC) {
            uint32_t* Aw = As[1 - pbuf];
            uint32_t* Bw = Bs[1 - pbuf];
#pragma unroll
            for (int i = 0; i < 4; i++) {
                Aw[aAd[i]] = pack_bf16(pa[i].x, pa[i].y);
                Aw[aAd[i] + 4] = pack_bf16(pa[i].z, pa[i].w);
                Bw[bAd[i]] = pack_bf16(pb[i].x, pb[i].y);
                Bw[bAd[i] + 2] = pack_bf16(pb[i].z, pb[i].w);
            }
        }
        __syncthreads();
    }

    const int rbase = m0 + wr * 32 + (lane >> 2);
    const int cbase = n0 + wc * 64 + (lane & 3) * 2;
#pragma unroll
    for (int i = 0; i < 2; i++) {
#pragma unroll
        for (int j = 0; j < 8; j++) {
            int col = cbase + j * 8;
            float2 v0 = make_float2(cacc[i][j][0], cacc[i][j][1]);
            float2 v1 = make_float2(cacc[i][j][2], cacc[i][j][3]);
            if (p.bias) {
                float b0 = p.bias[col], b1 = p.bias[col + 1];
                v0.x += b0; v0.y += b1; v1.x += b0; v1.y += b1;
            }
            if (p.relu) {
                v0.x = fmaxf(v0.x, 0.f); v0.y = fmaxf(v0.y, 0.f);
                v1.x = fmaxf(v1.x, 0.f); v1.y = fmaxf(v1.y, 0.f);
            }
            int r0 = rbase + i * 16;
            *(float2*)(C + (size_t)r0 * N + col) = v0;
            *(float2*)(C + (size_t)(r0 + 8) * N + col) = v1;
        }
    }
}

__global__ void splitk_reduce(const float* __restrict__ part, const float* __restrict__ bias,
                              float* __restrict__ out, int MN, int N, int S)
{
    int i = blockIdx.x * 256 + threadIdx.x;
    if (i >= MN) return;
    float s = 0.f;
    for (int z = 0; z < S; z++) s += part[(size_t)z * MN + i];
    s += bias[i % N];
    out[i] = fmaxf(s, 0.f);
}

// ---------------- conv2-as-GEMM helpers ----------------
__global__ void pad_w2(const float* __restrict__ w, const float* __restrict__ b,
                       float* __restrict__ wp, float* __restrict__ bp)
{
    int idx = blockIdx.x * 256 + threadIdx.x;
    if (idx < 128 * 2048) {
        int r = idx >> 11;
        wp[idx] = (r < 48) ? w[(size_t)r * 2048 + (idx & 2047)] : 0.f;
    }
    if (idx < 128) bp[idx] = (idx < 48) ? b[idx] : 0.f;
}

__global__ void im2col_k(const float* __restrict__ pool, float* __restrict__ A)
{
    size_t idx = (size_t)blockIdx.x * 256 + threadIdx.x;
    int col = (int)(idx & 2047);
    int row = (int)(idx >> 11);
    int b = row / 144, p = row - b * 144;
    int y = p / 12, x = p - y * 12;
    int ic = col >> 4, t = col & 15, rr = t >> 2, ss = t & 3;
    A[idx] = pool[((size_t)(b * 128 + ic)) * 225 + (y + rr) * 15 + (x + ss)];
}

__global__ void repack_c2(const float* __restrict__ CC, float* __restrict__ c2)
{
    int idx = blockIdx.x * 256 + threadIdx.x;
    int p = idx % 144;
    int t = idx / 144;
    int oc = t % 48, b = t / 48;
    c2[idx] = CC[((size_t)(b * 144 + p)) * 128 + oc];
}

// ---------------- patch extraction ----------------
__global__ void patch_kernel(const float* __restrict__ X, float* __restrict__ v)
{
    int idx = blockIdx.x * 256 + threadIdx.x;
    int f = idx % DIN1;
    int tmp = idx / DIN1;
    int b = tmp % SB;
    int t = tmp / SB;
    int w = t >> 3, h = t & 7;
    int c = f >> 4, rs = f & 15, rr = rs >> 2, s = rs & 3;
    v[idx] = X[((size_t)(b * 3 + c) * 32 + (h * 4 + rr)) * 32 + (w * 4 + s)];
}

// ---------------- LSTM pointwise (sums two K-split partials) ----------------
__global__ void lstm_step(const float* __restrict__ xgA, const float* __restrict__ xgB,
                          const float* __restrict__ gA,  const float* __restrict__ gB,
                          const float* __restrict__ gA2, const float* __restrict__ gB2,
                          const float* __restrict__ bihA, const float* __restrict__ bhhA,
                          const float* __restrict__ bihB, const float* __restrict__ bhhB,
                          float* hA, float* cA, float* hB, float* cB,
                          float* dstA, float* dstB, int dstStride)
{
    int z = blockIdx.z;
    int idx = blockIdx.x * 256 + threadIdx.x;
    const float* xg  = z ? xgB  : xgA;
    const float* g   = z ? gB   : gA;
    const float* g2  = z ? gB2  : gA2;
    const float* bih = z ? bihB : bihA;
    const float* bhh = z ? bhhB : bhhA;
    float* h = z ? hB : hA;
    float* c = z ? cB : cA;
    float* dst = z ? dstB : dstA;

    int b = idx / HH, j = idx - b * HH;
    size_t base = (size_t)b * GG + j;
    float gi = xg[base]       + g[base]       + g2[base]       + bih[j]       + bhh[j];
    float gf = xg[base + 320] + g[base + 320] + g2[base + 320] + bih[j + 320] + bhh[j + 320];
    float gg = xg[base + 640] + g[base + 640] + g2[base + 640] + bih[j + 640] + bhh[j + 640];
    float go = xg[base + 960] + g[base + 960] + g2[base + 960] + bih[j + 960] + bhh[j + 960];
    float iv = 1.f / (1.f + expf(-gi));
    float fv = 1.f / (1.f + expf(-gf));
    float gv = tanhf(gg);
    float ov = 1.f / (1.f + expf(-go));
    float cn = fv * c[idx] + iv * gv;
    c[idx] = cn;
    float hn = ov * tanhf(cn);
    h[idx] = hn;
    dst[(size_t)b * dstStride + j] = hn;
}

// ---------------- conv1+relu+pool ----------------
__global__ void conv1_pool(const float* __restrict__ X, const float* __restrict__ w,
                           const float* __restrict__ bias, float* __restrict__ out)
{
    int idx = blockIdx.x * 256 + threadIdx.x;
    int p = idx % 225;
    int tmp = idx / 225;
    int oc = tmp % 128;
    int b = tmp / 128;
    int y = p / 15, x = p % 15;
    float bv = bias[oc];
    float a00 = bv, a01 = bv, a10 = bv, a11 = bv;
    const float* wp = w + oc * 27;
    const float* xb = X + (size_t)b * 3 * 1024;
    int oy = 2 * y, ox = 2 * x;
#pragma unroll
    for (int c = 0; c < 3; c++)
#pragma unroll
        for (int rr = 0; rr < 3; rr++) {
            const float* xr0 = xb + c * 1024 + (oy + rr) * 32 + ox;
            const float* xr1 = xr0 + 32;
#pragma unroll
            for (int s = 0; s < 3; s++) {
                float wv = wp[c * 9 + rr * 3 + s];
                a00 += xr0[s] * wv;
                a01 += xr0[s + 1] * wv;
                a10 += xr1[s] * wv;
                a11 += xr1[s + 1] * wv;
            }
        }
    float m = fmaxf(fmaxf(a00, a01), fmaxf(a10, a11));
    out[idx] = fmaxf(m, 0.f);
}

// ---------------- batchnorm ----------------
__global__ void bn_stats(const float* __restrict__ x, int C, int HW,
                         float* __restrict__ mean, float* __restrict__ istd)
{
    int c = blockIdx.x;
    int n = SB * HW;
    double s = 0.0, qq = 0.0;
    for (int i = threadIdx.x; i < n; i += blockDim.x) {
        int b = i / HW, p = i - b * HW;
        float v = x[((size_t)b * C + c) * HW + p];
        s += v; qq += (double)v * v;
    }
    __shared__ double sh1[256], sh2[256];
    sh1[threadIdx.x] = s; sh2[threadIdx.x] = qq;
    __syncthreads();
    for (int st = 128; st > 0; st >>= 1) {
        if (threadIdx.x < st) { sh1[threadIdx.x] += sh1[threadIdx.x + st]; sh2[threadIdx.x] += sh2[threadIdx.x + st]; }
        __syncthreads();
    }
    if (threadIdx.x == 0) {
        double m = sh1[0] / n;
        double var = sh2[0] / n - m * m;
        mean[c] = (float)m;
        istd[c] = rsqrtf((float)var + 1e-5f);
    }
}

__global__ void bn_apply(float* __restrict__ x, int C, int HW,
                         const float* __restrict__ mean, const float* __restrict__ istd,
                         const float* __restrict__ gamma, const float* __restrict__ beta)
{
    int idx = blockIdx.x * 256 + threadIdx.x;
    int c = (idx / HW) % C;
    x[idx] = (x[idx] - mean[c]) * istd[c] * gamma[c] + beta[c];
}

// ---------------- fc + log_softmax ----------------
__global__ void fc_logsoftmax(const float* __restrict__ d1, const float* __restrict__ d2,
                              const float* __restrict__ w, const float* __restrict__ bias,
                              float* __restrict__ out)
{
    int b = blockIdx.x;
    int tid = threadIdx.x;
    float acc[10];
#pragma unroll
    for (int j = 0; j < 10; j++) acc[j] = 0.f;
    for (int k = tid; k < 2048; k += 128) {
        float v1 = d1[(size_t)b * 2048 + k];
        float v2 = d2[(size_t)b * 2048 + k];
#pragma unroll
        for (int j = 0; j < 10; j++)
            acc[j] += v1 * w[j * 4096 + k] + v2 * w[j * 4096 + 2048 + k];
    }
    __shared__ float sh[10][128];
#pragma unroll
    for (int j = 0; j < 10; j++) sh[j][tid] = acc[j];
    __syncthreads();
    for (int st = 64; st > 0; st >>= 1) {
        if (tid < st) {
#pragma unroll
            for (int j = 0; j < 10; j++) sh[j][tid] += sh[j][tid + st];
        }
        __syncthreads();
    }
    if (tid == 0) {
        float lg[10], mx = -1e30f;
#pragma unroll
        for (int j = 0; j < 10; j++) { lg[j] = sh[j][0] + bias[j]; mx = fmaxf(mx, lg[j]); }
        float se = 0.f;
#pragma unroll
        for (int j = 0; j < 10; j++) se += expf(lg[j] - mx);
        float lse = mx + logf(se);
#pragma unroll
        for (int j = 0; j < 10; j++) out[b * 10 + j] = lg[j] - lse;
    }
}

// ---------------- host ----------------
static void launch_rec(const float* h0, const float* W0, const float* h1, const float* W1,
                       float* gates)
{
    MArgs p;
    p.A0 = h0; p.B0 = W0; p.C0 = gates;
    p.A1 = h1; p.B1 = W1; p.C1 = nullptr;
    p.M = SB; p.N = GG; p.K = HH; p.bias = nullptr; p.relu = 0;
    p.splitK = 1; p.recDual = 1; p.kIdx = -1;
    dim3 grid(GG / 128, SB / 128, 4);
    bf16_gemm<<<grid, 256>>>(p);
}
static void launch_bf(const float* A0, const float* B0, float* C0,
                      const float* A1, const float* B1, float* C1,
                      int M, int N, int K, const float* bias, int relu, int nz, int splitK,
                      int kIdx, cudaStream_t st)
{
    MArgs p;
    p.A0 = A0; p.B0 = B0; p.C0 = C0;
    p.A1 = A1; p.B1 = B1; p.C1 = C1;
    p.M = M; p.N = N; p.K = K; p.bias = bias; p.relu = relu;
    p.splitK = splitK; p.recDual = 0; p.kIdx = kIdx;
    int gz = (splitK > 1) ? ((kIdx >= 0) ? 1 : splitK) : nz;
    dim3 grid(N / 128, M / 128, gz);
    bf16_gemm<<<grid, 256, 0, st>>>(p);
}

extern "C" void kernel_launch(void* const* d_in, const int* in_sizes, int n_in,
                              void* d_out, int out_size)
{
    const float* X       = (const float*)d_in[0];
    const float* conv1_w = (const float*)d_in[1];
    const float* conv1_b = (const float*)d_in[2];
    const float* bn1_g   = (const float*)d_in[3];
    const float* bn1_b   = (const float*)d_in[4];
    const float* conv2_w = (const float*)d_in[5];
    const float* conv2_b = (const float*)d_in[6];
    const float* bn2_g   = (const float*)d_in[7];
    const float* bn2_b   = (const float*)d_in[8];
    const float *Wih[4], *Whh[4], *bih[4], *bhh[4];
    for (int i = 0; i < 4; i++) {
        Wih[i] = (const float*)d_in[9  + 4 * i];
        Whh[i] = (const float*)d_in[10 + 4 * i];
        bih[i] = (const float*)d_in[11 + 4 * i];
        bhh[i] = (const float*)d_in[12 + 4 * i];
    }
    const float* dense1_w = (const float*)d_in[25];
    const float* dense1_b = (const float*)d_in[26];
    const float* dense2_w = (const float*)d_in[27];
    const float* dense2_b = (const float*)d_in[28];
    const float* fc_w     = (const float*)d_in[29];
    const float* fc_b     = (const float*)d_in[30];

    // one-time stream/event infra
    static cudaStream_t sCNN = nullptr;
    static cudaEvent_t evRoot = nullptr, evXG = nullptr, evSide = nullptr;
    static cudaEvent_t evS1[8], evS2[8];
    if (sCNN == nullptr) {
        cudaStreamCreateWithFlags(&sCNN, cudaStreamNonBlocking);
        cudaEventCreateWithFlags(&evRoot, cudaEventDisableTiming);
        cudaEventCreateWithFlags(&evXG, cudaEventDisableTiming);
        cudaEventCreateWithFlags(&evSide, cudaEventDisableTiming);
        for (int i = 0; i < 8; i++) {
            cudaEventCreateWithFlags(&evS1[i], cudaEventDisableTiming);
            cudaEventCreateWithFlags(&evS2[i], cudaEventDisableTiming);
        }
    }

    float *vfw, *XGA, *XGB, *XGA2, *XGB2, *vfm, *hfm, *state, *gates, *pool, *c2, *d1, *d2;
    float *part, *part2, *mean, *istd, *im2col, *cc, *w2pad, *b2pad;
    cudaGetSymbolAddress((void**)&vfw,    g_vfw);
    cudaGetSymbolAddress((void**)&XGA,    g_XGA);
    cudaGetSymbolAddress((void**)&XGB,    g_XGB);
    cudaGetSymbolAddress((void**)&XGA2,   g_XGA2);
    cudaGetSymbolAddress((void**)&XGB2,   g_XGB2);
    cudaGetSymbolAddress((void**)&vfm,    g_vfm);
    cudaGetSymbolAddress((void**)&hfm,    g_hfm);
    cudaGetSymbolAddress((void**)&state,  g_state);
    cudaGetSymbolAddress((void**)&gates,  g_gates);
    cudaGetSymbolAddress((void**)&pool,   g_pool);
    cudaGetSymbolAddress((void**)&c2,     g_c2);
    cudaGetSymbolAddress((void**)&d1,     g_d1);
    cudaGetSymbolAddress((void**)&d2,     g_d2);
    cudaGetSymbolAddress((void**)&part,   g_part);
    cudaGetSymbolAddress((void**)&part2,  g_part2);
    cudaGetSymbolAddress((void**)&mean,   g_mean);
    cudaGetSymbolAddress((void**)&istd,   g_istd);
    cudaGetSymbolAddress((void**)&im2col, g_im2col);
    cudaGetSymbolAddress((void**)&cc,     g_cc);
    cudaGetSymbolAddress((void**)&w2pad,  g_w2pad);
    cudaGetSymbolAddress((void**)&b2pad,  g_b2pad);

    float* h0 = state;
    float* h1 = state + SB * HH;
    float* c0 = state + 2 * SB * HH;
    float* c1 = state + 3 * SB * HH;
    float* gp = gates;

    // ===== fork point =====
    cudaEventRecord(evRoot, 0);
    cudaStreamWaitEvent(sCNN, evRoot, 0);

    // ===== CNN branch (sCNN stream) =====
    conv1_pool<<<(SB * 128 * 225) / 256, 256, 0, sCNN>>>(X, conv1_w, conv1_b, pool);
    bn_stats<<<128, 256, 0, sCNN>>>(pool, 128, 225, mean, istd);
    bn_apply<<<(SB * 128 * 225) / 256, 256, 0, sCNN>>>(pool, 128, 225, mean, istd, bn1_g, bn1_b);
    pad_w2<<<(128 * 2048) / 256, 256, 0, sCNN>>>(conv2_w, conv2_b, w2pad, b2pad);
    im2col_k<<<589824, 256, 0, sCNN>>>(pool, im2col);
    launch_bf(im2col, w2pad, cc, nullptr, nullptr, nullptr, 73728, 128, 2048, b2pad, 1, 1, 1, -1, sCNN);
    repack_c2<<<(SB * 48 * 144) / 256, 256, 0, sCNN>>>(cc, c2);
    bn_stats<<<48, 256, 0, sCNN>>>(c2, 48, 144, mean, istd);
    bn_apply<<<(SB * 48 * 144) / 256, 256, 0, sCNN>>>(c2, 48, 144, mean, istd, bn2_g, bn2_b);
    launch_bf(c2, dense2_w, part2, nullptr, nullptr, nullptr, SB, 2048, 6912, nullptr, 0, 1, 4, -1, sCNN);
    splitk_reduce<<<(SB * 2048 + 255) / 256, 256, 0, sCNN>>>(part2, dense2_b, d2, SB * 2048, 2048, 4);

    // ===== ReNet stage 1 (main stream), XG34 chunks pipelined on sCNN =====
    patch_kernel<<<(TT * SB * DIN1) / 256, 256>>>(X, vfw);
    launch_bf(vfw, Wih[0], XGA, vfw, Wih[1], XGB, TT * SB, GG, DIN1, nullptr, 0, 2, 1, -1, 0);
    cudaMemsetAsync(state, 0, 4 * SB * HH * sizeof(float), 0);
    for (int t = 0; t < TT; t++) {
        launch_rec(h0, Whh[0], h1, Whh[1], gp);
        lstm_step<<<dim3((SB * HH) / 256, 1, 2), 256>>>(
            XGA + (size_t)t * SB * GG, XGB + (size_t)(TT - 1 - t) * SB * GG,
            gp, gp + (size_t)SB * GG, gp + 2 * (size_t)SB * GG, gp + 3 * (size_t)SB * GG,
            bih[0], bhh[0], bih[1], bhh[1],
            h0, c0, h1, c1,
            vfm + (size_t)t * SB * 2 * HH, vfm + (size_t)t * SB * 2 * HH + HH, 2 * HH);
        if ((t & 7) == 7) {
            int k = t >> 3;
            cudaEventRecord(evS1[k], 0);
            cudaStreamWaitEvent(sCNN, evS1[k], 0);
            const float* Ach = vfm + (size_t)k * 8 * SB * 2 * HH;     // rows [k*4096, +4096)
            launch_bf(Ach, Wih[2], XGA2 + (size_t)k * 4096 * GG,
                      Ach, Wih[3], XGB2 + (size_t)k * 4096 * GG,
                      4096, GG, DIN2, nullptr, 0, 2, 1, -1, sCNN);
        }
    }

    // stage 2 needs all XG34 chunks (reverse direction reads position 63 first)
    cudaEventRecord(evXG, sCNN);
    cudaStreamWaitEvent(0, evXG, 0);

    // ===== ReNet stage 2, dense1 partials pipelined on sCNN =====
    cudaMemsetAsync(state, 0, 4 * SB * HH * sizeof(float), 0);
    for (int t = 0; t < TT; t++) {
        launch_rec(h0, Whh[2], h1, Whh[3], gp);
        lstm_step<<<dim3((SB * HH) / 256, 1, 2), 256>>>(
            XGA2 + (size_t)t * SB * GG, XGB2 + (size_t)(TT - 1 - t) * SB * GG,
            gp, gp + (size_t)SB * GG, gp + 2 * (size_t)SB * GG, gp + 3 * (size_t)SB * GG,
            bih[2], bhh[2], bih[3], bhh[3],
            h0, c0, h1, c1,
            hfm + (size_t)t * 2 * HH, hfm + (size_t)t * 2 * HH + HH, TT * 2 * HH);
        if ((t & 7) == 7) {
            int z = t >> 3;
            cudaEventRecord(evS2[z], 0);
            cudaStreamWaitEvent(sCNN, evS2[z], 0);
            // dense1 split-K partial z: K-chunk [z*5120, (z+1)*5120) = timesteps [8z, 8z+8)
            launch_bf(hfm, dense1_w, part, nullptr, nullptr, nullptr,
                      SB, 2048, TT * 2 * HH, nullptr, 0, 1, 8, z, sCNN);
        }
    }

    // ===== join side stream (dense1 partials + d2), reduce, fc =====
    cudaEventRecord(evSide, sCNN);
    cudaStreamWaitEvent(0, evSide, 0);
    splitk_reduce<<<(SB * 2048 + 255) / 256, 256>>>(part, dense1_b, d1, SB * 2048, 2048, 8);
    fc_logsoftmax<<<SB, 128>>>(d1, d2, fc_w, fc_b, (float*)d_out);
}

// round 16
// speedup vs baseline: 1.0089x; 1.0089x over previous
#include <cuda_runtime.h>
#include <math.h>
#include <stdint.h>

#define SB   512
#define HH   320
#define GG   1280
#define TT   64
#define DIN1 48
#define DIN2 640

// ---------------- device scratch ----------------
__device__ float g_vfw[TT * SB * DIN1];
__device__ float g_XGA[TT * SB * GG];
__device__ float g_XGB[TT * SB * GG];
__device__ float g_vfm[TT * SB * 2 * HH];
__device__ float g_hfm[SB * TT * 2 * HH];
__device__ float g_state[4 * SB * HH];
__device__ float g_gates[4 * SB * GG];      // recurrent split-K partials
__device__ float g_pool[SB * 128 * 15 * 15];
__device__ float g_c2[SB * 48 * 12 * 12];
__device__ float g_d1[SB * 2048];
__device__ float g_d2[SB * 2048];
__device__ float g_part[8 * SB * 2048];     // dense1 split-K partials
__device__ float g_part2[4 * SB * 2048];    // dense2 split-K partials
__device__ float g_mean[128];
__device__ float g_istd[128];
__device__ float g_im2col[73728 * 2048];
__device__ float g_cc[73728 * 128];
__device__ float g_w2pad[128 * 2048];
__device__ float g_b2pad[128];

// ---------------- mma helpers ----------------
__device__ __forceinline__ uint32_t pack_bf16(float lo, float hi) {
    uint32_t r;
    asm("cvt.rn.bf16x2.f32 %0, %1, %2;" : "=r"(r) : "f"(hi), "f"(lo));
    return r;
}
__device__ __forceinline__ void mma_bf16(float* c, const uint32_t* a, const uint32_t* b) {
    asm volatile(
        "mma.sync.aligned.m16n8k16.row.col.f32.bf16.bf16.f32 "
        "{%0,%1,%2,%3}, {%4,%5,%6,%7}, {%8,%9}, {%0,%1,%2,%3};"
        : "+f"(c[0]), "+f"(c[1]), "+f"(c[2]), "+f"(c[3])
        : "r"(a[0]), "r"(a[1]), "r"(a[2]), "r"(a[3]), "r"(b[0]), "r"(b[1]));
}

#define BKC 32

// ---------------- bf16 GEMM: C[M,N] = A[M,K] @ B[N,K]^T ----------------
// recDual=1: blockIdx.z = (ks<<1)|lstm; K halves -> partial buffers.
// splitK>1 && kIdx>=0: single K-chunk kIdx, grid.z=1, C -> C0 + kIdx*M*N.
struct MArgs {
    const float *A0, *B0; float* C0;
    const float *A1, *B1; float* C1;
    int M, N, K;
    const float* bias; int relu;
    int splitK;
    int recDual;
    int kIdx;
};

__global__ __launch_bounds__(256) void bf16_gemm(MArgs p)
{
    __shared__ uint32_t As[2][2048];
    __shared__ uint32_t Bs[2][2048];

    const float *A, *B; float* C;
    int kOff = 0, kLen = p.K;
    if (p.recDual) {
        int lstm = blockIdx.z & 1, ks = blockIdx.z >> 1;
        A = lstm ? p.A1 : p.A0;
        B = lstm ? p.B1 : p.B0;
        kLen = p.K >> 1;
        kOff = ks * kLen;
        C = p.C0 + (size_t)(lstm + 2 * ks) * p.M * p.N;
    } else if (p.splitK > 1) {
        A = p.A0; B = p.B0;
        kLen = p.K / p.splitK;
        int z = (p.kIdx >= 0) ? p.kIdx : (int)blockIdx.z;
        kOff = z * kLen;
        C = p.C0 + (size_t)z * p.M * p.N;
    } else {
        A = blockIdx.z ? p.A1 : p.A0;
        B = blockIdx.z ? p.B1 : p.B0;
        C = blockIdx.z ? p.C1 : p.C0;
    }
    const int N = p.N, K = p.K;
    const int m0 = blockIdx.y * 128, n0 = blockIdx.x * 128;
    const int tid = threadIdx.x, lane = tid & 31, wid = tid >> 5;
    const int wr = wid & 3, wc = wid >> 2;
    const int kEnd = kOff + kLen;
    const int NC = (kLen + BKC - 1) / BKC;

    uint32_t aAd[4], bAd[4];
    int fr[4], fq[4];
#pragma unroll
    for (int i = 0; i < 4; i++) {
        int f = tid + i * 256;
        int r = f >> 3, q = f & 7;
        fr[i] = r; fq[i] = q;
        int kt = q >> 2;
        int ps = (2 * q) & 7;
        { int mt = r >> 4, r16 = r & 15;
          int laneA = (r16 & 7) * 4 + (ps & 3);
          int regA = (ps >> 2) * 2 + (r16 >> 3);
          aAd[i] = (uint32_t)(((kt * 8 + mt) * 32 + laneA) * 4 + regA); }
        { int nt = r >> 3, n8 = r & 7;
          int laneB = n8 * 4 + (ps & 3);
          int regB = ps >> 2;
          bAd[i] = (uint32_t)(((kt * 16 + nt) * 32 + laneB) * 2 + regB); }
    }

    float cacc[2][8][4];
#pragma unroll
    for (int i = 0; i < 2; i++)
#pragma unroll
        for (int j = 0; j < 8; j++)
#pragma unroll
            for (int v = 0; v < 4; v++) cacc[i][j][v] = 0.f;

    float4 pa[4], pb[4];
#pragma unroll
    for (int i = 0; i < 4; i++) {
        int gk = kOff + fq[i] * 4;
        pa[i] = make_float4(0.f, 0.f, 0.f, 0.f);
        pb[i] = pa[i];
        if (gk < kEnd) {
            pa[i] = *(const float4*)(A + (size_t)(m0 + fr[i]) * K + gk);
            pb[i] = *(const float4*)(B + (size_t)(n0 + fr[i]) * K + gk);
        }
    }
#pragma unroll
    for (int i = 0; i < 4; i++) {
        As[0][aAd[i]] = pack_bf16(pa[i].x, pa[i].y);
        As[0][aAd[i] + 4] = pack_bf16(pa[i].z, pa[i].w);
        Bs[0][bAd[i]] = pack_bf16(pb[i].x, pb[i].y);
        Bs[0][bAd[i] + 2] = pack_bf16(pb[i].z, pb[i].w);
    }
    __syncthreads();

    for (int ch = 0; ch < NC; ch++) {
        int pbuf = ch & 1;
        if (ch + 1 < NC) {
#pragma unroll
            for (int i = 0; i < 4; i++) {
                int gk = kOff + (ch + 1) * BKC + fq[i] * 4;
                pa[i] = make_float4(0.f, 0.f, 0.f, 0.f);
                pb[i] = pa[i];
                if (gk < kEnd) {
                    pa[i] = *(const float4*)(A + (size_t)(m0 + fr[i]) * K + gk);
                    pb[i] = *(const float4*)(B + (size_t)(n0 + fr[i]) * K + gk);
                }
            }
        }
        const uint32_t* Ab = As[pbuf];
        const uint32_t* Bb = Bs[pbuf];
#pragma unroll
        for (int kt = 0; kt < 2; kt++) {
            uint32_t af[2][4], bf[8][2];
#pragma unroll
            for (int i = 0; i < 2; i++) {
                int mt = wr * 2 + i;
                uint4 v = *(const uint4*)&Ab[((kt * 8 + mt) * 32 + lane) * 4];
                af[i][0] = v.x; af[i][1] = v.y; af[i][2] = v.z; af[i][3] = v.w;
            }
#pragma unroll
            for (int j = 0; j < 8; j++) {
                int nt = wc * 8 + j;
                uint2 v = *(const uint2*)&Bb[((kt * 16 + nt) * 32 + lane) * 2];
                bf[j][0] = v.x; bf[j][1] = v.y;
            }
#pragma unroll
            for (int i = 0; i < 2; i++)
#pragma unroll
                for (int j = 0; j < 8; j++)
                    mma_bf16(cacc[i][j], af[i], bf[j]);
        }
        if (ch + 1 < NC) {
            uint32_t* Aw = As[1 - pbuf];
            uint32_t* Bw = Bs[1 - pbuf];
#pragma unroll
            for (int i = 0; i < 4; i++) {
                Aw[aAd[i]] = pack_bf16(pa[i].x, pa[i].y);
                Aw[aAd[i] + 4] = pack_bf16(pa[i].z, pa[i].w);
                Bw[bAd[i]] = pack_bf16(pb[i].x, pb[i].y);
                Bw[bAd[i] + 2] = pack_bf16(pb[i].z, pb[i].w);
            }
        }
        __syncthreads();
    }

    const int rbase = m0 + wr * 32 + (lane >> 2);
    const int cbase = n0 + wc * 64 + (lane & 3) * 2;
#pragma unroll
    for (int i = 0; i < 2; i++) {
#pragma unroll
        for (int j = 0; j < 8; j++) {
            int col = cbase + j * 8;
            float2 v0 = make_float2(cacc[i][j][0], cacc[i][j][1]);
            float2 v1 = make_float2(cacc[i][j][2], cacc[i][j][3]);
            if (p.bias) {
                float b0 = p.bias[col], b1 = p.bias[col + 1];
                v0.x += b0; v0.y += b1; v1.x += b0; v1.y += b1;
            }
            if (p.relu) {
                v0.x = fmaxf(v0.x, 0.f); v0.y = fmaxf(v0.y, 0.f);
                v1.x = fmaxf(v1.x, 0.f); v1.y = fmaxf(v1.y, 0.f);
            }
            int r0 = rbase + i * 16;
            *(float2*)(C + (size_t)r0 * N + col) = v0;
            *(float2*)(C + (size_t)(r0 + 8) * N + col) = v1;
        }
    }
}

__global__ void splitk_reduce(const float* __restrict__ part, const float* __restrict__ bias,
                              float* __restrict__ out, int MN, int N, int S)
{
    int i = blockIdx.x * 256 + threadIdx.x;
    if (i >= MN) return;
    float s = 0.f;
    for (int z = 0; z < S; z++) s += part[(size_t)z * MN + i];
    s += bias[i % N];
    out[i] = fmaxf(s, 0.f);
}

// ---------------- conv2-as-GEMM helpers ----------------
__global__ void pad_w2(const float* __restrict__ w, const float* __restrict__ b,
                       float* __restrict__ wp, float* __restrict__ bp)
{
    int idx = blockIdx.x * 256 + threadIdx.x;
    if (idx < 128 * 2048) {
        int r = idx >> 11;
        wp[idx] = (r < 48) ? w[(size_t)r * 2048 + (idx & 2047)] : 0.f;
    }
    if (idx < 128) bp[idx] = (idx < 48) ? b[idx] : 0.f;
}

__global__ void im2col_k(const float* __restrict__ pool, float* __restrict__ A)
{
    size_t idx = (size_t)blockIdx.x * 256 + threadIdx.x;
    int col = (int)(idx & 2047);
    int row = (int)(idx >> 11);
    int b = row / 144, p = row - b * 144;
    int y = p / 12, x = p - y * 12;
    int ic = col >> 4, t = col & 15, rr = t >> 2, ss = t & 3;
    A[idx] = pool[((size_t)(b * 128 + ic)) * 225 + (y + rr) * 15 + (x + ss)];
}

__global__ void repack_c2(const float* __restrict__ CC, float* __restrict__ c2)
{
    int idx = blockIdx.x * 256 + threadIdx.x;
    int p = idx % 144;
    int t = idx / 144;
    int oc = t % 48, b = t / 48;
    c2[idx] = CC[((size_t)(b * 144 + p)) * 128 + oc];
}

// ---------------- patch extraction ----------------
__global__ void patch_kernel(const float* __restrict__ X, float* __restrict__ v)
{
    int idx = blockIdx.x * 256 + threadIdx.x;
    int f = idx % DIN1;
    int tmp = idx / DIN1;
    int b = tmp % SB;
    int t = tmp / SB;
    int w = t >> 3, h = t & 7;
    int c = f >> 4, rs = f & 15, rr = rs >> 2, s = rs & 3;
    v[idx] = X[((size_t)(b * 3 + c) * 32 + (h * 4 + rr)) * 32 + (w * 4 + s)];
}

// ---------------- LSTM pointwise (sums two K-split partials) ----------------
__global__ void lstm_step(const float* __restrict__ xgA, const float* __restrict__ xgB,
                          const float* __restrict__ gA,  const float* __restrict__ gB,
                          const float* __restrict__ gA2, const float* __restrict__ gB2,
                          const float* __restrict__ bihA, const float* __restrict__ bhhA,
                          const float* __restrict__ bihB, const float* __restrict__ bhhB,
                          float* hA, float* cA, float* hB, float* cB,
                          float* dstA, float* dstB, int dstStride)
{
    int z = blockIdx.z;
    int idx = blockIdx.x * 256 + threadIdx.x;
    const float* xg  = z ? xgB  : xgA;
    const float* g   = z ? gB   : gA;
    const float* g2  = z ? gB2  : gA2;
    const float* bih = z ? bihB : bihA;
    const float* bhh = z ? bhhB : bhhA;
    float* h = z ? hB : hA;
    float* c = z ? cB : cA;
    float* dst = z ? dstB : dstA;

    int b = idx / HH, j = idx - b * HH;
    size_t base = (size_t)b * GG + j;
    float gi = xg[base]       + g[base]       + g2[base]       + bih[j]       + bhh[j];
    float gf = xg[base + 320] + g[base + 320] + g2[base + 320] + bih[j + 320] + bhh[j + 320];
    float gg = xg[base + 640] + g[base + 640] + g2[base + 640] + bih[j + 640] + bhh[j + 640];
    float go = xg[base + 960] + g[base + 960] + g2[base + 960] + bih[j + 960] + bhh[j + 960];
    float iv = 1.f / (1.f + expf(-gi));
    float fv = 1.f / (1.f + expf(-gf));
    float gv = tanhf(gg);
    float ov = 1.f / (1.f + expf(-go));
    float cn = fv * c[idx] + iv * gv;
    c[idx] = cn;
    float hn = ov * tanhf(cn);
    h[idx] = hn;
    dst[(size_t)b * dstStride + j] = hn;
}

// ---------------- conv1+relu+pool ----------------
__global__ void conv1_pool(const float* __restrict__ X, const float* __restrict__ w,
                           const float* __restrict__ bias, float* __restrict__ out)
{
    int idx = blockIdx.x * 256 + threadIdx.x;
    int p = idx % 225;
    int tmp = idx / 225;
    int oc = tmp % 128;
    int b = tmp / 128;
    int y = p / 15, x = p % 15;
    float bv = bias[oc];
    float a00 = bv, a01 = bv, a10 = bv, a11 = bv;
    const float* wp = w + oc * 27;
    const float* xb = X + (size_t)b * 3 * 1024;
    int oy = 2 * y, ox = 2 * x;
#pragma unroll
    for (int c = 0; c < 3; c++)
#pragma unroll
        for (int rr = 0; rr < 3; rr++) {
            const float* xr0 = xb + c * 1024 + (oy + rr) * 32 + ox;
            const float* xr1 = xr0 + 32;
#pragma unroll
            for (int s = 0; s < 3; s++) {
                float wv = wp[c * 9 + rr * 3 + s];
                a00 += xr0[s] * wv;
                a01 += xr0[s + 1] * wv;
                a10 += xr1[s] * wv;
                a11 += xr1[s + 1] * wv;
            }
        }
    float m = fmaxf(fmaxf(a00, a01), fmaxf(a10, a11));
    out[idx] = fmaxf(m, 0.f);
}

// ---------------- batchnorm ----------------
__global__ void bn_stats(const float* __restrict__ x, int C, int HW,
                         float* __restrict__ mean, float* __restrict__ istd)
{
    int c = blockIdx.x;
    int n = SB * HW;
    double s = 0.0, qq = 0.0;
    for (int i = threadIdx.x; i < n; i += blockDim.x) {
        int b = i / HW, p = i - b * HW;
        float v = x[((size_t)b * C + c) * HW + p];
        s += v; qq += (double)v * v;
    }
    __shared__ double sh1[256], sh2[256];
    sh1[threadIdx.x] = s; sh2[threadIdx.x] = qq;
    __syncthreads();
    for (int st = 128; st > 0; st >>= 1) {
        if (threadIdx.x < st) { sh1[threadIdx.x] += sh1[threadIdx.x + st]; sh2[threadIdx.x] += sh2[threadIdx.x + st]; }
        __syncthreads();
    }
    if (threadIdx.x == 0) {
        double m = sh1[0] / n;
        double var = sh2[0] / n - m * m;
        mean[c] = (float)m;
        istd[c] = rsqrtf((float)var + 1e-5f);
    }
}

__global__ void bn_apply(float* __restrict__ x, int C, int HW,
                         const float* __restrict__ mean, const float* __restrict__ istd,
                         const float* __restrict__ gamma, const float* __restrict__ beta)
{
    int idx = blockIdx.x * 256 + threadIdx.x;
    int c = (idx / HW) % C;
    x[idx] = (x[idx] - mean[c]) * istd[c] * gamma[c] + beta[c];
}

// ---------------- fc + log_softmax ----------------
__global__ void fc_logsoftmax(const float* __restrict__ d1, const float* __restrict__ d2,
                              const float* __restrict__ w, const float* __restrict__ bias,
                              float* __restrict__ out)
{
    int b = blockIdx.x;
    int tid = threadIdx.x;
    float acc[10];
#pragma unroll
    for (int j = 0; j < 10; j++) acc[j] = 0.f;
    for (int k = tid; k < 2048; k += 128) {
        float v1 = d1[(size_t)b * 2048 + k];
        float v2 = d2[(size_t)b * 2048 + k];
#pragma unroll
        for (int j = 0; j < 10; j++)
            acc[j] += v1 * w[j * 4096 + k] + v2 * w[j * 4096 + 2048 + k];
    }
    __shared__ float sh[10][128];
#pragma unroll
    for (int j = 0; j < 10; j++) sh[j][tid] = acc[j];
    __syncthreads();
    for (int st = 64; st > 0; st >>= 1) {
        if (tid < st) {
#pragma unroll
            for (int j = 0; j < 10; j++) sh[j][tid] += sh[j][tid + st];
        }
        __syncthreads();
    }
    if (tid == 0) {
        float lg[10], mx = -1e30f;
#pragma unroll
        for (int j = 0; j < 10; j++) { lg[j] = sh[j][0] + bias[j]; mx = fmaxf(mx, lg[j]); }
        float se = 0.f;
#pragma unroll
        for (int j = 0; j < 10; j++) se += expf(lg[j] - mx);
        float lse = mx + logf(se);
#pragma unroll
        for (int j = 0; j < 10; j++) out[b * 10 + j] = lg[j] - lse;
    }
}

// ---------------- host ----------------
static void launch_rec(const float* h0, const float* W0, const float* h1, const float* W1,
                       float* gates)
{
    MArgs p;
    p.A0 = h0; p.B0 = W0; p.C0 = gates;
    p.A1 = h1; p.B1 = W1; p.C1 = nullptr;
    p.M = SB; p.N = GG; p.K = HH; p.bias = nullptr; p.relu = 0;
    p.splitK = 1; p.recDual = 1; p.kIdx = -1;
    dim3 grid(GG / 128, SB / 128, 4);
    bf16_gemm<<<grid, 256>>>(p);
}
static void launch_bf(const float* A0, const float* B0, float* C0,
                      const float* A1, const float* B1, float* C1,
                      int M, int N, int K, const float* bias, int relu, int nz, int splitK,
                      int kIdx, cudaStream_t st)
{
    MArgs p;
    p.A0 = A0; p.B0 = B0; p.C0 = C0;
    p.A1 = A1; p.B1 = B1; p.C1 = C1;
    p.M = M; p.N = N; p.K = K; p.bias = bias; p.relu = relu;
    p.splitK = splitK; p.recDual = 0; p.kIdx = kIdx;
    int gz = (splitK > 1) ? ((kIdx >= 0) ? 1 : splitK) : nz;
    dim3 grid(N / 128, M / 128, gz);
    bf16_gemm<<<grid, 256, 0, st>>>(p);
}

extern "C" void kernel_launch(void* const* d_in, const int* in_sizes, int n_in,
                              void* d_out, int out_size)
{
    const float* X       = (const float*)d_in[0];
    const float* conv1_w = (const float*)d_in[1];
    const float* conv1_b = (const float*)d_in[2];
    const float* bn1_g   = (const float*)d_in[3];
    const float* bn1_b   = (const float*)d_in[4];
    const float* conv2_w = (const float*)d_in[5];
    const float* conv2_b = (const float*)d_in[6];
    const float* bn2_g   = (const float*)d_in[7];
    const float* bn2_b   = (const float*)d_in[8];
    const float *Wih[4], *Whh[4], *bih[4], *bhh[4];
    for (int i = 0; i < 4; i++) {
        Wih[i] = (const float*)d_in[9  + 4 * i];
        Whh[i] = (const float*)d_in[10 + 4 * i];
        bih[i] = (const float*)d_in[11 + 4 * i];
        bhh[i] = (const float*)d_in[12 + 4 * i];
    }
    const float* dense1_w = (const float*)d_in[25];
    const float* dense1_b = (const float*)d_in[26];
    const float* dense2_w = (const float*)d_in[27];
    const float* dense2_b = (const float*)d_in[28];
    const float* fc_w     = (const float*)d_in[29];
    const float* fc_b     = (const float*)d_in[30];

    // one-time stream/event infra
    static cudaStream_t sCNN = nullptr;
    static cudaEvent_t evRoot = nullptr, evSide = nullptr;
    static cudaEvent_t evS2[8];
    if (sCNN == nullptr) {
        cudaStreamCreateWithFlags(&sCNN, cudaStreamNonBlocking);
        cudaEventCreateWithFlags(&evRoot, cudaEventDisableTiming);
        cudaEventCreateWithFlags(&evSide, cudaEventDisableTiming);
        for (int i = 0; i < 8; i++)
            cudaEventCreateWithFlags(&evS2[i], cudaEventDisableTiming);
    }

    float *vfw, *XGA, *XGB, *vfm, *hfm, *state, *gates, *pool, *c2, *d1, *d2;
    float *part, *part2, *mean, *istd, *im2col, *cc, *w2pad, *b2pad;
    cudaGetSymbolAddress((void**)&vfw,    g_vfw);
    cudaGetSymbolAddress((void**)&XGA,    g_XGA);
    cudaGetSymbolAddress((void**)&XGB,    g_XGB);
    cudaGetSymbolAddress((void**)&vfm,    g_vfm);
    cudaGetSymbolAddress((void**)&hfm,    g_hfm);
    cudaGetSymbolAddress((void**)&state,  g_state);
    cudaGetSymbolAddress((void**)&gates,  g_gates);
    cudaGetSymbolAddress((void**)&pool,   g_pool);
    cudaGetSymbolAddress((void**)&c2,     g_c2);
    cudaGetSymbolAddress((void**)&d1,     g_d1);
    cudaGetSymbolAddress((void**)&d2,     g_d2);
    cudaGetSymbolAddress((void**)&part,   g_part);
    cudaGetSymbolAddress((void**)&part2,  g_part2);
    cudaGetSymbolAddress((void**)&mean,   g_mean);
    cudaGetSymbolAddress((void**)&istd,   g_istd);
    cudaGetSymbolAddress((void**)&im2col, g_im2col);
    cudaGetSymbolAddress((void**)&cc,     g_cc);
    cudaGetSymbolAddress((void**)&w2pad,  g_w2pad);
    cudaGetSymbolAddress((void**)&b2pad,  g_b2pad);

    float* h0 = state;
    float* h1 = state + SB * HH;
    float* c0 = state + 2 * SB * HH;
    float* c1 = state + 3 * SB * HH;
    float* gp = gates;

    // ===== fork point =====
    cudaEventRecord(evRoot, 0);
    cudaStreamWaitEvent(sCNN, evRoot, 0);

    // ===== CNN branch (sCNN stream) =====
    conv1_pool<<<(SB * 128 * 225) / 256, 256, 0, sCNN>>>(X, conv1_w, conv1_b, pool);
    bn_stats<<<128, 256, 0, sCNN>>>(pool, 128, 225, mean, istd);
    bn_apply<<<(SB * 128 * 225) / 256, 256, 0, sCNN>>>(pool, 128, 225, mean, istd, bn1_g, bn1_b);
    pad_w2<<<(128 * 2048) / 256, 256, 0, sCNN>>>(conv2_w, conv2_b, w2pad, b2pad);
    im2col_k<<<589824, 256, 0, sCNN>>>(pool, im2col);
    launch_bf(im2col, w2pad, cc, nullptr, nullptr, nullptr, 73728, 128, 2048, b2pad, 1, 1, 1, -1, sCNN);
    repack_c2<<<(SB * 48 * 144) / 256, 256, 0, sCNN>>>(cc, c2);
    bn_stats<<<48, 256, 0, sCNN>>>(c2, 48, 144, mean, istd);
    bn_apply<<<(SB * 48 * 144) / 256, 256, 0, sCNN>>>(c2, 48, 144, mean, istd, bn2_g, bn2_b);
    launch_bf(c2, dense2_w, part2, nullptr, nullptr, nullptr, SB, 2048, 6912, nullptr, 0, 1, 4, -1, sCNN);
    splitk_reduce<<<(SB * 2048 + 255) / 256, 256, 0, sCNN>>>(part2, dense2_b, d2, SB * 2048, 2048, 4);

    // ===== ReNet stage 1 (main stream) =====
    patch_kernel<<<(TT * SB * DIN1) / 256, 256>>>(X, vfw);
    launch_bf(vfw, Wih[0], XGA, vfw, Wih[1], XGB, TT * SB, GG, DIN1, nullptr, 0, 2, 1, -1, 0);
    cudaMemsetAsync(state, 0, 4 * SB * HH * sizeof(float), 0);
    for (int t = 0; t < TT; t++) {
        launch_rec(h0, Whh[0], h1, Whh[1], gp);
        lstm_step<<<dim3((SB * HH) / 256, 1, 2), 256>>>(
            XGA + (size_t)t * SB * GG, XGB + (size_t)(TT - 1 - t) * SB * GG,
            gp, gp + (size_t)SB * GG, gp + 2 * (size_t)SB * GG, gp + 3 * (size_t)SB * GG,
            bih[0], bhh[0], bih[1], bhh[1],
            h0, c0, h1, c1,
            vfm + (size_t)t * SB * 2 * HH, vfm + (size_t)t * SB * 2 * HH + HH, 2 * HH);
    }

    // ===== XG34 (single main-stream launch, as in R14) =====
    launch_bf(vfm, Wih[2], XGA, vfm, Wih[3], XGB, TT * SB, GG, DIN2, nullptr, 0, 2, 1, -1, 0);
    cudaMemsetAsync(state, 0, 4 * SB * HH * sizeof(float), 0);

    // ===== ReNet stage 2; dense1 partials (64-CTA launches) pipelined on sCNN =====
    for (int t = 0; t < TT; t++) {
        launch_rec(h0, Whh[2], h1, Whh[3], gp);
        lstm_step<<<dim3((SB * HH) / 256, 1, 2), 256>>>(
            XGA + (size_t)t * SB * GG, XGB + (size_t)(TT - 1 - t) * SB * GG,
            gp, gp + (size_t)SB * GG, gp + 2 * (size_t)SB * GG, gp + 3 * (size_t)SB * GG,
            bih[2], bhh[2], bih[3], bhh[3],
            h0, c0, h1, c1,
            hfm + (size_t)t * 2 * HH, hfm + (size_t)t * 2 * HH + HH, TT * 2 * HH);
        if ((t & 7) == 7) {
            int z = t >> 3;
            cudaEventRecord(evS2[z], 0);
            cudaStreamWaitEvent(sCNN, evS2[z], 0);
            // dense1 split-K partial z: K-chunk [z*5120,(z+1)*5120) = timesteps [8z,8z+8)
            launch_bf(hfm, dense1_w, part, nullptr, nullptr, nullptr,
                      SB, 2048, TT * 2 * HH, nullptr, 0, 1, 8, z, sCNN);
        }
    }

    // ===== join side stream (dense1 partials + d2), reduce, fc =====
    cudaEventRecord(evSide, sCNN);
    cudaStreamWaitEvent(0, evSide, 0);
    splitk_reduce<<<(SB * 2048 + 255) / 256, 256>>>(part, dense1_b, d1, SB * 2048, 2048, 8);
    fc_logsoftmax<<<SB, 128>>>(d1, d2, fc_w, fc_b, (float*)d_out);
}

// round 17
// speedup vs baseline: 1.0800x; 1.0705x over previous
#include <cuda_runtime.h>
#include <math.h>
#include <stdint.h>

#define SB   512
#define HH   320
#define GG   1280
#define TT   64
#define DIN1 48
#define DIN2 640

// ---------------- device scratch ----------------
__device__ float g_vfw[TT * SB * DIN1];
__device__ float g_XGA[TT * SB * GG];
__device__ float g_XGB[TT * SB * GG];
__device__ float g_vfm[TT * SB * 2 * HH];
__device__ float g_hfm[SB * TT * 2 * HH];
__device__ float g_state[4 * SB * HH];
__device__ float g_gates[2 * SB * GG];      // recurrent gates (one buffer per LSTM)
__device__ float g_pool[SB * 128 * 15 * 15];
__device__ float g_c2[SB * 48 * 12 * 12];
__device__ float g_d1[SB * 2048];
__device__ float g_d2[SB * 2048];
__device__ float g_part[8 * SB * 2048];
__device__ float g_part2[4 * SB * 2048];
__device__ float g_mean[128];
__device__ float g_istd[128];
__device__ float g_bsum[4 * GG];            // bih+bhh per rnn
__device__ float g_im2col[73728 * 2048];
__device__ float g_cc[73728 * 128];
__device__ float g_w2pad[128 * 2048];
__device__ float g_b2pad[128];

// ---------------- mma helpers ----------------
__device__ __forceinline__ uint32_t pack_bf16(float lo, float hi) {
    uint32_t r;
    asm("cvt.rn.bf16x2.f32 %0, %1, %2;" : "=r"(r) : "f"(hi), "f"(lo));
    return r;
}
__device__ __forceinline__ void mma_bf16(float* c, const uint32_t* a, const uint32_t* b) {
    asm volatile(
        "mma.sync.aligned.m16n8k16.row.col.f32.bf16.bf16.f32 "
        "{%0,%1,%2,%3}, {%4,%5,%6,%7}, {%8,%9}, {%0,%1,%2,%3};"
        : "+f"(c[0]), "+f"(c[1]), "+f"(c[2]), "+f"(c[3])
        : "r"(a[0]), "r"(a[1]), "r"(a[2]), "r"(a[3]), "r"(b[0]), "r"(b[1]));
}

#define BKC 32

// ---------------- bf16 GEMM: C[M,N] = A[M,K] @ B[N,K]^T ----------------
// recDual=1: blockIdx.z = lstm; full K; C -> C0 + lstm*M*N.
struct MArgs {
    const float *A0, *B0; float* C0;
    const float *A1, *B1; float* C1;
    int M, N, K;
    const float *bias0, *bias1; int relu;
    int splitK;
    int recDual;
};

__global__ __launch_bounds__(256) void bf16_gemm(MArgs p)
{
    __shared__ uint32_t As[2][2048];
    __shared__ uint32_t Bs[2][2048];

    const float *A, *B, *bias; float* C;
    int kOff = 0, kLen = p.K;
    if (p.recDual) {
        int lstm = blockIdx.z;
        A = lstm ? p.A1 : p.A0;
        B = lstm ? p.B1 : p.B0;
        C = p.C0 + (size_t)lstm * p.M * p.N;
        bias = nullptr;
    } else if (p.splitK > 1) {
        A = p.A0; B = p.B0; bias = p.bias0;
        kLen = p.K / p.splitK;
        kOff = blockIdx.z * kLen;
        C = p.C0 + (size_t)blockIdx.z * p.M * p.N;
    } else {
        A = blockIdx.z ? p.A1 : p.A0;
        B = blockIdx.z ? p.B1 : p.B0;
        C = blockIdx.z ? p.C1 : p.C0;
        bias = blockIdx.z ? p.bias1 : p.bias0;
    }
    const int N = p.N, K = p.K;
    const int m0 = blockIdx.y * 128, n0 = blockIdx.x * 128;
    const int tid = threadIdx.x, lane = tid & 31, wid = tid >> 5;
    const int wr = wid & 3, wc = wid >> 2;
    const int kEnd = kOff + kLen;
    const int NC = (kLen + BKC - 1) / BKC;

    uint32_t aAd[4], bAd[4];
    int fr[4], fq[4];
#pragma unroll
    for (int i = 0; i < 4; i++) {
        int f = tid + i * 256;
        int r = f >> 3, q = f & 7;
        fr[i] = r; fq[i] = q;
        int kt = q >> 2;
        int ps = (2 * q) & 7;
        { int mt = r >> 4, r16 = r & 15;
          int laneA = (r16 & 7) * 4 + (ps & 3);
          int regA = (ps >> 2) * 2 + (r16 >> 3);
          aAd[i] = (uint32_t)(((kt * 8 + mt) * 32 + laneA) * 4 + regA); }
        { int nt = r >> 3, n8 = r & 7;
          int laneB = n8 * 4 + (ps & 3);
          int regB = ps >> 2;
          bAd[i] = (uint32_t)(((kt * 16 + nt) * 32 + laneB) * 2 + regB); }
    }

    float cacc[2][8][4];
#pragma unroll
    for (int i = 0; i < 2; i++)
#pragma unroll
        for (int j = 0; j < 8; j++)
#pragma unroll
            for (int v = 0; v < 4; v++) cacc[i][j][v] = 0.f;

    float4 pa[4], pb[4];
#pragma unroll
    for (int i = 0; i < 4; i++) {
        int gk = kOff + fq[i] * 4;
        pa[i] = make_float4(0.f, 0.f, 0.f, 0.f);
        pb[i] = pa[i];
        if (gk < kEnd) {
            pa[i] = *(const float4*)(A + (size_t)(m0 + fr[i]) * K + gk);
            pb[i] = *(const float4*)(B + (size_t)(n0 + fr[i]) * K + gk);
        }
    }
#pragma unroll
    for (int i = 0; i < 4; i++) {
        As[0][aAd[i]] = pack_bf16(pa[i].x, pa[i].y);
        As[0][aAd[i] + 4] = pack_bf16(pa[i].z, pa[i].w);
        Bs[0][bAd[i]] = pack_bf16(pb[i].x, pb[i].y);
        Bs[0][bAd[i] + 2] = pack_bf16(pb[i].z, pb[i].w);
    }
    __syncthreads();

    for (int ch = 0; ch < NC; ch++) {
        int pbuf = ch & 1;
        if (ch + 1 < NC) {
#pragma unroll
            for (int i = 0; i < 4; i++) {
                int gk = kOff + (ch + 1) * BKC + fq[i] * 4;
                pa[i] = make_float4(0.f, 0.f, 0.f, 0.f);
                pb[i] = pa[i];
                if (gk < kEnd) {
                    pa[i] = *(const float4*)(A + (size_t)(m0 + fr[i]) * K + gk);
                    pb[i] = *(const float4*)(B + (size_t)(n0 + fr[i]) * K + gk);
                }
            }
        }
        const uint32_t* Ab = As[pbuf];
        const uint32_t* Bb = Bs[pbuf];
#pragma unroll
        for (int kt = 0; kt < 2; kt++) {
            uint32_t af[2][4], bf[8][2];
#pragma unroll
            for (int i = 0; i < 2; i++) {
                int mt = wr * 2 + i;
                uint4 v = *(const uint4*)&Ab[((kt * 8 + mt) * 32 + lane) * 4];
                af[i][0] = v.x; af[i][1] = v.y; af[i][2] = v.z; af[i][3] = v.w;
            }
#pragma unroll
            for (int j = 0; j < 8; j++) {
                int nt = wc * 8 + j;
                uint2 v = *(const uint2*)&Bb[((kt * 16 + nt) * 32 + lane) * 2];
                bf[j][0] = v.x; bf[j][1] = v.y;
            }
#pragma unroll
            for (int i = 0; i < 2; i++)
#pragma unroll
                for (int j = 0; j < 8; j++)
                    mma_bf16(cacc[i][j], af[i], bf[j]);
        }
        if (ch + 1 < NC) {
            uint32_t* Aw = As[1 - pbuf];
            uint32_t* Bw = Bs[1 - pbuf];
#pragma unroll
            for (int i = 0; i < 4; i++) {
                Aw[aAd[i]] = pack_bf16(pa[i].x, pa[i].y);
                Aw[aAd[i] + 4] = pack_bf16(pa[i].z, pa[i].w);
                Bw[bAd[i]] = pack_bf16(pb[i].x, pb[i].y);
                Bw[bAd[i] + 2] = pack_bf16(pb[i].z, pb[i].w);
            }
        }
        __syncthreads();
    }

    const int rbase = m0 + wr * 32 + (lane >> 2);
    const int cbase = n0 + wc * 64 + (lane & 3) * 2;
#pragma unroll
    for (int i = 0; i < 2; i++) {
#pragma unroll
        for (int j = 0; j < 8; j++) {
            int col = cbase + j * 8;
            float2 v0 = make_float2(cacc[i][j][0], cacc[i][j][1]);
            float2 v1 = make_float2(cacc[i][j][2], cacc[i][j][3]);
            if (bias) {
                float b0 = bias[col], b1 = bias[col + 1];
                v0.x += b0; v0.y += b1; v1.x += b0; v1.y += b1;
            }
            if (p.relu) {
                v0.x = fmaxf(v0.x, 0.f); v0.y = fmaxf(v0.y, 0.f);
                v1.x = fmaxf(v1.x, 0.f); v1.y = fmaxf(v1.y, 0.f);
            }
            int r0 = rbase + i * 16;
            *(float2*)(C + (size_t)r0 * N + col) = v0;
            *(float2*)(C + (size_t)(r0 + 8) * N + col) = v1;
        }
    }
}

__global__ void splitk_reduce(const float* __restrict__ part, const float* __restrict__ bias,
                              float* __restrict__ out, int MN, int N, int S)
{
    int i = blockIdx.x * 256 + threadIdx.x;
    if (i >= MN) return;
    float s = 0.f;
    for (int z = 0; z < S; z++) s += part[(size_t)z * MN + i];
    s += bias[i % N];
    out[i] = fmaxf(s, 0.f);
}

__global__ void sum_bias(const float* __restrict__ bih0, const float* __restrict__ bhh0,
                         const float* __restrict__ bih1, const float* __restrict__ bhh1,
                         const float* __restrict__ bih2, const float* __restrict__ bhh2,
                         const float* __restrict__ bih3, const float* __restrict__ bhh3,
                         float* __restrict__ out)
{
    int i = blockIdx.x * 256 + threadIdx.x;
    if (i >= GG) return;
    out[i]          = bih0[i] + bhh0[i];
    out[i + GG]     = bih1[i] + bhh1[i];
    out[i + 2 * GG] = bih2[i] + bhh2[i];
    out[i + 3 * GG] = bih3[i] + bhh3[i];
}

// ---------------- conv2-as-GEMM helpers ----------------
__global__ void pad_w2(const float* __restrict__ w, const float* __restrict__ b,
                       float* __restrict__ wp, float* __restrict__ bp)
{
    int idx = blockIdx.x * 256 + threadIdx.x;
    if (idx < 128 * 2048) {
        int r = idx >> 11;
        wp[idx] = (r < 48) ? w[(size_t)r * 2048 + (idx & 2047)] : 0.f;
    }
    if (idx < 128) bp[idx] = (idx < 48) ? b[idx] : 0.f;
}

__global__ void im2col_k(const float* __restrict__ pool, float* __restrict__ A)
{
    size_t idx = (size_t)blockIdx.x * 256 + threadIdx.x;
    int col = (int)(idx & 2047);
    int row = (int)(idx >> 11);
    int b = row / 144, p = row - b * 144;
    int y = p / 12, x = p - y * 12;
    int ic = col >> 4, t = col & 15, rr = t >> 2, ss = t & 3;
    A[idx] = pool[((size_t)(b * 128 + ic)) * 225 + (y + rr) * 15 + (x + ss)];
}

__global__ void repack_c2(const float* __restrict__ CC, float* __restrict__ c2)
{
    int idx = blockIdx.x * 256 + threadIdx.x;
    int p = idx % 144;
    int t = idx / 144;
    int oc = t % 48, b = t / 48;
    c2[idx] = CC[((size_t)(b * 144 + p)) * 128 + oc];
}

// ---------------- patch extraction ----------------
__global__ void patch_kernel(const float* __restrict__ X, float* __restrict__ v)
{
    int idx = blockIdx.x * 256 + threadIdx.x;
    int f = idx % DIN1;
    int tmp = idx / DIN1;
    int b = tmp % SB;
    int t = tmp / SB;
    int w = t >> 3, h = t & 7;
    int c = f >> 4, rs = f & 15, rr = rs >> 2, s = rs & 3;
    v[idx] = X[((size_t)(b * 3 + c) * 32 + (h * 4 + rr)) * 32 + (w * 4 + s)];
}

// ---------------- LSTM pointwise (single gate buffer; biases pre-folded into xg) ----------------
__global__ void lstm_step(const float* __restrict__ xgA, const float* __restrict__ xgB,
                          const float* __restrict__ gA,  const float* __restrict__ gB,
                          float* hA, float* cA, float* hB, float* cB,
                          float* dstA, float* dstB, int dstStride)
{
    int z = blockIdx.z;
    int idx = blockIdx.x * 256 + threadIdx.x;
    const float* xg = z ? xgB : xgA;
    const float* g  = z ? gB  : gA;
    float* h = z ? hB : hA;
    float* c = z ? cB : cA;
    float* dst = z ? dstB : dstA;

    int b = idx / HH, j = idx - b * HH;
    size_t base = (size_t)b * GG + j;
    float gi = xg[base]       + g[base];
    float gf = xg[base + 320] + g[base + 320];
    float gg = xg[base + 640] + g[base + 640];
    float go = xg[base + 960] + g[base + 960];
    float iv = 1.f / (1.f + expf(-gi));
    float fv = 1.f / (1.f + expf(-gf));
    float gv = tanhf(gg);
    float ov = 1.f / (1.f + expf(-go));
    float cn = fv * c[idx] + iv * gv;
    c[idx] = cn;
    float hn = ov * tanhf(cn);
    h[idx] = hn;
    dst[(size_t)b * dstStride + j] = hn;
}

// ---------------- conv1+relu+pool ----------------
__global__ void conv1_pool(const float* __restrict__ X, const float* __restrict__ w,
                           const float* __restrict__ bias, float* __restrict__ out)
{
    int idx = blockIdx.x * 256 + threadIdx.x;
    int p = idx % 225;
    int tmp = idx / 225;
    int oc = tmp % 128;
    int b = tmp / 128;
    int y = p / 15, x = p % 15;
    float bv = bias[oc];
    float a00 = bv, a01 = bv, a10 = bv, a11 = bv;
    const float* wp = w + oc * 27;
    const float* xb = X + (size_t)b * 3 * 1024;
    int oy = 2 * y, ox = 2 * x;
#pragma unroll
    for (int c = 0; c < 3; c++)
#pragma unroll
        for (int rr = 0; rr < 3; rr++) {
            const float* xr0 = xb + c * 1024 + (oy + rr) * 32 + ox;
            const float* xr1 = xr0 + 32;
#pragma unroll
            for (int s = 0; s < 3; s++) {
                float wv = wp[c * 9 + rr * 3 + s];
                a00 += xr0[s] * wv;
                a01 += xr0[s + 1] * wv;
                a10 += xr1[s] * wv;
                a11 += xr1[s + 1] * wv;
            }
        }
    float m = fmaxf(fmaxf(a00, a01), fmaxf(a10, a11));
    out[idx] = fmaxf(m, 0.f);
}

// ---------------- batchnorm ----------------
__global__ void bn_stats(const float* __restrict__ x, int C, int HW,
                         float* __restrict__ mean, float* __restrict__ istd)
{
    int c = blockIdx.x;
    int n = SB * HW;
    double s = 0.0, qq = 0.0;
    for (int i = threadIdx.x; i < n; i += blockDim.x) {
        int b = i / HW, p = i - b * HW;
        float v = x[((size_t)b * C + c) * HW + p];
        s += v; qq += (double)v * v;
    }
    __shared__ double sh1[256], sh2[256];
    sh1[threadIdx.x] = s; sh2[threadIdx.x] = qq;
    __syncthreads();
    for (int st = 128; st > 0; st >>= 1) {
        if (threadIdx.x < st) { sh1[threadIdx.x] += sh1[threadIdx.x + st]; sh2[threadIdx.x] += sh2[threadIdx.x + st]; }
        __syncthreads();
    }
    if (threadIdx.x == 0) {
        double m = sh1[0] / n;
        double var = sh2[0] / n - m * m;
        mean[c] = (float)m;
        istd[c] = rsqrtf((float)var + 1e-5f);
    }
}

__global__ void bn_apply(float* __restrict__ x, int C, int HW,
                         const float* __restrict__ mean, const float* __restrict__ istd,
                         const float* __restrict__ gamma, const float* __restrict__ beta)
{
    int idx = blockIdx.x * 256 + threadIdx.x;
    int c = (idx / HW) % C;
    x[idx] = (x[idx] - mean[c]) * istd[c] * gamma[c] + beta[c];
}

// ---------------- fc + log_softmax ----------------
__global__ void fc_logsoftmax(const float* __restrict__ d1, const float* __restrict__ d2,
                              const float* __restrict__ w, const float* __restrict__ bias,
                              float* __restrict__ out)
{
    int b = blockIdx.x;
    int tid = threadIdx.x;
    float acc[10];
#pragma unroll
    for (int j = 0; j < 10; j++) acc[j] = 0.f;
    for (int k = tid; k < 2048; k += 128) {
        float v1 = d1[(size_t)b * 2048 + k];
        float v2 = d2[(size_t)b * 2048 + k];
#pragma unroll
        for (int j = 0; j < 10; j++)
            acc[j] += v1 * w[j * 4096 + k] + v2 * w[j * 4096 + 2048 + k];
    }
    __shared__ float sh[10][128];
#pragma unroll
    for (int j = 0; j < 10; j++) sh[j][tid] = acc[j];
    __syncthreads();
    for (int st = 64; st > 0; st >>= 1) {
        if (tid < st) {
#pragma unroll
            for (int j = 0; j < 10; j++) sh[j][tid] += sh[j][tid + st];
        }
        __syncthreads();
    }
    if (tid == 0) {
        float lg[10], mx = -1e30f;
#pragma unroll
        for (int j = 0; j < 10; j++) { lg[j] = sh[j][0] + bias[j]; mx = fmaxf(mx, lg[j]); }
        float se = 0.f;
#pragma unroll
        for (int j = 0; j < 10; j++) se += expf(lg[j] - mx);
        float lse = mx + logf(se);
#pragma unroll
        for (int j = 0; j < 10; j++) out[b * 10 + j] = lg[j] - lse;
    }
}

// ---------------- host ----------------
static void launch_rec(const float* h0, const float* W0, const float* h1, const float* W1,
                       float* gates)
{
    MArgs p;
    p.A0 = h0; p.B0 = W0; p.C0 = gates;
    p.A1 = h1; p.B1 = W1; p.C1 = nullptr;
    p.M = SB; p.N = GG; p.K = HH; p.bias0 = nullptr; p.bias1 = nullptr; p.relu = 0;
    p.splitK = 1; p.recDual = 1;
    dim3 grid(GG / 128, SB / 128, 2);
    bf16_gemm<<<grid, 256>>>(p);
}
static void launch_bf(const float* A0, const float* B0, float* C0,
                      const float* A1, const float* B1, float* C1,
                      int M, int N, int K, const float* bias0, const float* bias1,
                      int relu, int nz, int splitK, cudaStream_t st)
{
    MArgs p;
    p.A0 = A0; p.B0 = B0; p.C0 = C0;
    p.A1 = A1; p.B1 = B1; p.C1 = C1;
    p.M = M; p.N = N; p.K = K; p.bias0 = bias0; p.bias1 = bias1; p.relu = relu;
    p.splitK = splitK; p.recDual = 0;
    dim3 grid(N / 128, M / 128, splitK > 1 ? splitK : nz);
    bf16_gemm<<<grid, 256, 0, st>>>(p);
}

extern "C" void kernel_launch(void* const* d_in, const int* in_sizes, int n_in,
                              void* d_out, int out_size)
{
    const float* X       = (const float*)d_in[0];
    const float* conv1_w = (const float*)d_in[1];
    const float* conv1_b = (const float*)d_in[2];
    const float* bn1_g   = (const float*)d_in[3];
    const float* bn1_b   = (const float*)d_in[4];
    const float* conv2_w = (const float*)d_in[5];
    const float* conv2_b = (const float*)d_in[6];
    const float* bn2_g   = (const float*)d_in[7];
    const float* bn2_b   = (const float*)d_in[8];
    const float *Wih[4], *Whh[4], *bih[4], *bhh[4];
    for (int i = 0; i < 4; i++) {
        Wih[i] = (const float*)d_in[9  + 4 * i];
        Whh[i] = (const float*)d_in[10 + 4 * i];
        bih[i] = (const float*)d_in[11 + 4 * i];
        bhh[i] = (const float*)d_in[12 + 4 * i];
    }
    const float* dense1_w = (const float*)d_in[25];
    const float* dense1_b = (const float*)d_in[26];
    const float* dense2_w = (const float*)d_in[27];
    const float* dense2_b = (const float*)d_in[28];
    const float* fc_w     = (const float*)d_in[29];
    const float* fc_b     = (const float*)d_in[30];

    // one-time stream/event infra
    static cudaStream_t sCNN = nullptr;
    static cudaEvent_t evRoot = nullptr, evCNN = nullptr;
    if (sCNN == nullptr) {
        cudaStreamCreateWithFlags(&sCNN, cudaStreamNonBlocking);
        cudaEventCreateWithFlags(&evRoot, cudaEventDisableTiming);
        cudaEventCreateWithFlags(&evCNN, cudaEventDisableTiming);
    }

    float *vfw, *XGA, *XGB, *vfm, *hfm, *state, *gates, *pool, *c2, *d1, *d2;
    float *part, *part2, *mean, *istd, *bsum, *im2col, *cc, *w2pad, *b2pad;
    cudaGetSymbolAddress((void**)&vfw,    g_vfw);
    cudaGetSymbolAddress((void**)&XGA,    g_XGA);
    cudaGetSymbolAddress((void**)&XGB,    g_XGB);
    cudaGetSymbolAddress((void**)&vfm,    g_vfm);
    cudaGetSymbolAddress((void**)&hfm,    g_hfm);
    cudaGetSymbolAddress((void**)&state,  g_state);
    cudaGetSymbolAddress((void**)&gates,  g_gates);
    cudaGetSymbolAddress((void**)&pool,   g_pool);
    cudaGetSymbolAddress((void**)&c2,     g_c2);
    cudaGetSymbolAddress((void**)&d1,     g_d1);
    cudaGetSymbolAddress((void**)&d2,     g_d2);
    cudaGetSymbolAddress((void**)&part,   g_part);
    cudaGetSymbolAddress((void**)&part2,  g_part2);
    cudaGetSymbolAddress((void**)&mean,   g_mean);
    cudaGetSymbolAddress((void**)&istd,   g_istd);
    cudaGetSymbolAddress((void**)&bsum,   g_bsum);
    cudaGetSymbolAddress((void**)&im2col, g_im2col);
    cudaGetSymbolAddress((void**)&cc,     g_cc);
    cudaGetSymbolAddress((void**)&w2pad,  g_w2pad);
    cudaGetSymbolAddress((void**)&b2pad,  g_b2pad);

    float* h0 = state;
    float* h1 = state + SB * HH;
    float* c0 = state + 2 * SB * HH;
    float* c1 = state + 3 * SB * HH;
    float* gp = gates;

    // ===== fork point =====
    cudaEventRecord(evRoot, 0);
    cudaStreamWaitEvent(sCNN, evRoot, 0);

    // ===== CNN branch (sCNN stream) =====
    conv1_pool<<<(SB * 128 * 225) / 256, 256, 0, sCNN>>>(X, conv1_w, conv1_b, pool);
    bn_stats<<<128, 256, 0, sCNN>>>(pool, 128, 225, mean, istd);
    bn_apply<<<(SB * 128 * 225) / 256, 256, 0, sCNN>>>(pool, 128, 225, mean, istd, bn1_g, bn1_b);
    pad_w2<<<(128 * 2048) / 256, 256, 0, sCNN>>>(conv2_w, conv2_b, w2pad, b2pad);
    im2col_k<<<589824, 256, 0, sCNN>>>(pool, im2col);
    launch_bf(im2col, w2pad, cc, nullptr, nullptr, nullptr, 73728, 128, 2048, b2pad, nullptr, 1, 1, 1, sCNN);
    repack_c2<<<(SB * 48 * 144) / 256, 256, 0, sCNN>>>(cc, c2);
    bn_stats<<<48, 256, 0, sCNN>>>(c2, 48, 144, mean, istd);
    bn_apply<<<(SB * 48 * 144) / 256, 256, 0, sCNN>>>(c2, 48, 144, mean, istd, bn2_g, bn2_b);
    launch_bf(c2, dense2_w, part2, nullptr, nullptr, nullptr, SB, 2048, 6912, nullptr, nullptr, 0, 1, 4, sCNN);
    splitk_reduce<<<(SB * 2048 + 255) / 256, 256, 0, sCNN>>>(part2, dense2_b, d2, SB * 2048, 2048, 4);
    cudaEventRecord(evCNN, sCNN);

    // ===== ReNet stage 1 (main stream) =====
    sum_bias<<<(GG + 255) / 256, 256>>>(bih[0], bhh[0], bih[1], bhh[1],
                                        bih[2], bhh[2], bih[3], bhh[3], bsum);
    patch_kernel<<<(TT * SB * DIN1) / 256, 256>>>(X, vfw);
    launch_bf(vfw, Wih[0], XGA, vfw, Wih[1], XGB, TT * SB, GG, DIN1,
              bsum, bsum + GG, 0, 2, 1, 0);
    cudaMemsetAsync(state, 0, 4 * SB * HH * sizeof(float), 0);
    for (int t = 0; t < TT; t++) {
        launch_rec(h0, Whh[0], h1, Whh[1], gp);
        lstm_step<<<dim3((SB * HH) / 256, 1, 2), 256>>>(
            XGA + (size_t)t * SB * GG, XGB + (size_t)(TT - 1 - t) * SB * GG,
            gp, gp + (size_t)SB * GG,
            h0, c0, h1, c1,
            vfm + (size_t)t * SB * 2 * HH, vfm + (size_t)t * SB * 2 * HH + HH, 2 * HH);
    }

    // ===== XG34 + ReNet stage 2 =====
    launch_bf(vfm, Wih[2], XGA, vfm, Wih[3], XGB, TT * SB, GG, DIN2,
              bsum + 2 * GG, bsum + 3 * GG, 0, 2, 1, 0);
    cudaMemsetAsync(state, 0, 4 * SB * HH * sizeof(float), 0);
    for (int t = 0; t < TT; t++) {
        launch_rec(h0, Whh[2], h1, Whh[3], gp);
        lstm_step<<<dim3((SB * HH) / 256, 1, 2), 256>>>(
            XGA + (size_t)t * SB * GG, XGB + (size_t)(TT - 1 - t) * SB * GG,
            gp, gp + (size_t)SB * GG,
            h0, c0, h1, c1,
            hfm + (size_t)t * 2 * HH, hfm + (size_t)t * 2 * HH + HH, TT * 2 * HH);
    }

    // ===== dense1 via split-K 8 (main stream) =====
    launch_bf(hfm, dense1_w, part, nullptr, nullptr, nullptr, SB, 2048, TT * 2 * HH,
              nullptr, nullptr, 0, 1, 8, 0);
    splitk_reduce<<<(SB * 2048 + 255) / 256, 256>>>(part, dense1_b, d1, SB * 2048, 2048, 8);

    // ===== join CNN branch, then fc + log_softmax =====
    cudaStreamWaitEvent(0, evCNN, 0);
    fc_logsoftmax<<<SB, 128>>>(d1, d2, fc_w, fc_b, (float*)d_out);
}